// round 6
// baseline (speedup 1.0000x reference)
#include <cuda_runtime.h>
#include <cstdint>

#define IN_F  4096
#define OUT_F 16384
#define NB    8      // batch vectors
#define NP    (NB/2) // batch pairs
#define RPW   8      // rows per warp
#define WARPS 8
#define THREADS (WARPS * 32)          // 256
#define ROWS_PER_CTA (RPW * WARPS)    // 64
#define NCHUNK (IN_F / 128)           // 32 chunks (4 cols/lane each)

__constant__ float NF4_CODE[16] = {
    -1.0f, -0.6961928009986877f, -0.5250730514526367f, -0.39491748809814453f,
    -0.28444138169288635f, -0.18477343022823334f, -0.09105003625154495f, 0.0f,
    0.07958029955625534f, 0.16093020141124725f, 0.24611230194568634f,
    0.33791524171829224f, 0.44070982933044434f, 0.5626170039176941f,
    0.7229568362236023f, 1.0f};

// ---- packed f32x2 helpers (Blackwell FFMA2 path: only reachable via PTX) ----
__device__ __forceinline__ unsigned long long pk2(float lo, float hi) {
    unsigned long long r;
    asm("mov.b64 %0, {%1, %2};" : "=l"(r)
        : "r"(__float_as_uint(lo)), "r"(__float_as_uint(hi)));
    return r;
}
__device__ __forceinline__ void upk2(unsigned long long v, float& lo, float& hi) {
    unsigned int a, b;
    asm("mov.b64 {%0, %1}, %2;" : "=r"(a), "=r"(b) : "l"(v));
    lo = __uint_as_float(a); hi = __uint_as_float(b);
}
__device__ __forceinline__ void fma2(unsigned long long& acc,
                                     unsigned long long a, unsigned long long b) {
    asm("fma.rn.f32x2 %0, %1, %2, %0;" : "+l"(acc) : "l"(a), "l"(b));
}

__global__ __launch_bounds__(THREADS, 1)
void nf4_qlinear_kernel(const float* __restrict__ x,
                        const int*   __restrict__ codes,
                        const float* __restrict__ absmax,
                        float*       __restrict__ out) {
    // NF4 table replicated per lane: tab[c*32 + lane] -> bank == lane
    __shared__ float tab[16 * 32];
    const int tid  = threadIdx.x;
    const int lane = tid & 31;
    const int warp = tid >> 5;
    #pragma unroll
    for (int i = tid; i < 16 * 32; i += THREADS) tab[i] = NF4_CODE[i >> 5];
    __syncthreads();

    const int row0   = blockIdx.x * ROWS_PER_CTA + warp * RPW;
    const int sel_hi = (lane >= 16);

    // acc[r][p] packs (batch 2p, batch 2p+1) partial dot products
    unsigned long long acc[RPW][NP];
    #pragma unroll
    for (int r = 0; r < RPW; ++r)
        #pragma unroll
        for (int p = 0; p < NP; ++p) acc[r][p] = 0ULL;

    // ---- code-burst loader: 8 independent LDG.128 for chunk jj ----
    auto load_codes = [&](int jj, int4* cv) {
        const int col = jj * 128 + lane * 4;
        #pragma unroll
        for (int r = 0; r < RPW; ++r)
            cv[r] = __ldcs(reinterpret_cast<const int4*>(
                codes + (size_t)(row0 + r) * IN_F + col));
    };

    // ---- consume one chunk ----
    auto consume = [&](int jj, const int4* cv) {
        const int col = jj * 128 + lane * 4;
        // cross-batch x pairs, reused by all 8 rows
        unsigned long long xp[NP][4];
        #pragma unroll
        for (int p = 0; p < NP; ++p) {
            const float4 xe = *reinterpret_cast<const float4*>(
                x + (2 * p)     * IN_F + col);
            const float4 xo = *reinterpret_cast<const float4*>(
                x + (2 * p + 1) * IN_F + col);
            xp[p][0] = pk2(xe.x, xo.x);
            xp[p][1] = pk2(xe.y, xo.y);
            xp[p][2] = pk2(xe.z, xo.z);
            xp[p][3] = pk2(xe.w, xo.w);
        }
        #pragma unroll
        for (int r = 0; r < RPW; ++r) {
            const float2 amv = *reinterpret_cast<const float2*>(
                absmax + (size_t)(row0 + r) * (IN_F / 64) + jj * 2);
            const float a = sel_hi ? amv.y : amv.x;
            const float w0 = tab[(cv[r].x << 5) + lane] * a;
            const float w1 = tab[(cv[r].y << 5) + lane] * a;
            const float w2 = tab[(cv[r].z << 5) + lane] * a;
            const float w3 = tab[(cv[r].w << 5) + lane] * a;
            const unsigned long long s0 = pk2(w0, w0);
            const unsigned long long s1 = pk2(w1, w1);
            const unsigned long long s2 = pk2(w2, w2);
            const unsigned long long s3 = pk2(w3, w3);
            #pragma unroll
            for (int p = 0; p < NP; ++p) {
                fma2(acc[r][p], s0, xp[p][0]);
                fma2(acc[r][p], s1, xp[p][1]);
                fma2(acc[r][p], s2, xp[p][2]);
                fma2(acc[r][p], s3, xp[p][3]);
            }
        }
    };

    // ---- software pipeline: prefetch next chunk's codes under compute ----
    int4 cvA[RPW], cvB[RPW];
    load_codes(0, cvA);
    #pragma unroll 1
    for (int j = 0; j < NCHUNK; j += 2) {
        load_codes(j + 1, cvB);        // in flight during consume of A
        consume(j, cvA);
        if (j + 2 < NCHUNK) load_codes(j + 2, cvA);   // in flight during B
        consume(j + 1, cvB);
    }

    // Warp-reduce each packed accumulator (both batches at once), store.
    #pragma unroll
    for (int r = 0; r < RPW; ++r) {
        #pragma unroll
        for (int p = 0; p < NP; ++p) {
            float se, so;
            upk2(acc[r][p], se, so);
            #pragma unroll
            for (int off = 16; off > 0; off >>= 1) {
                se += __shfl_xor_sync(0xffffffffu, se, off);
                so += __shfl_xor_sync(0xffffffffu, so, off);
            }
            if (lane == 0) {
                out[(size_t)(2 * p)     * OUT_F + row0 + r] = se;
                out[(size_t)(2 * p + 1) * OUT_F + row0 + r] = so;
            }
        }
    }
}

extern "C" void kernel_launch(void* const* d_in, const int* in_sizes, int n_in,
                              void* d_out, int out_size) {
    const float* x      = (const float*)d_in[0];   // [8,1,4096] f32
    const int*   codes  = (const int*)d_in[1];     // [16384,4096] i32 (0..15)
    const float* absmax = (const float*)d_in[2];   // [16384,64] f32
    float*       out    = (float*)d_out;           // [8,1,16384] f32

    (void)in_sizes; (void)n_in; (void)out_size;
    nf4_qlinear_kernel<<<OUT_F / ROWS_PER_CTA, THREADS>>>(x, codes, absmax, out);
}